// round 16
// baseline (speedup 1.0000x reference)
#include <cuda_runtime.h>
#include <cstdint>

#define EPS_ 0.001f

// Problem constants
#define NB   16
#define CIN  64
#define CO   64
#define TT   64
#define VV   384
#define PP   (TT*VV)          // 24576 positions per (n, channel)
#define XP_ELEMS  (NB*CO*PP)  // 25165824
#define CS_ELEMS  (NB*CO*VV)  // 393216

typedef unsigned long long ull;

// Scratch (no cudaMalloc allowed)
__device__ float g_xp[XP_ELEMS];
__device__ float g_colsum[CS_ELEMS];

// ---------------------------------------------------------------------------
// packed f32x2 helpers
// ---------------------------------------------------------------------------
__device__ __forceinline__ ull pack2(float lo, float hi) {
    ull r; asm("mov.b64 %0, {%1, %2};" : "=l"(r) : "f"(lo), "f"(hi)); return r;
}
__device__ __forceinline__ ull splat2(float v) {
    ull r; asm("mov.b64 %0, {%1, %1};" : "=l"(r) : "f"(v)); return r;
}
__device__ __forceinline__ void unpack2(ull p, float& lo, float& hi) {
    asm("mov.b64 {%0, %1}, %2;" : "=f"(lo), "=f"(hi) : "l"(p));
}
__device__ __forceinline__ ull fma2(ull a, ull b, ull c) {
    ull d; asm("fma.rn.f32x2 %0, %1, %2, %3;" : "=l"(d) : "l"(a), "l"(b), "l"(c)); return d;
}

// ---------------------------------------------------------------------------
// mbarrier helpers
// ---------------------------------------------------------------------------
__device__ __forceinline__ uint32_t smem_u32(const void* p) {
    uint32_t a;
    asm("{ .reg .u64 t; cvta.to.shared.u64 t, %1; cvt.u32.u64 %0, t; }" : "=r"(a) : "l"(p));
    return a;
}
__device__ __forceinline__ void mbar_init(uint32_t a, uint32_t cnt) {
    asm volatile("mbarrier.init.shared.b64 [%0], %1;" :: "r"(a), "r"(cnt) : "memory");
}
__device__ __forceinline__ void mbar_arrive(uint32_t a) {
    asm volatile("mbarrier.arrive.shared.b64 _, [%0];" :: "r"(a) : "memory");
}
__device__ __forceinline__ void mbar_wait(uint32_t a, uint32_t parity) {
    uint32_t done;
    asm volatile(
        "{\n\t.reg .pred p;\n\t"
        "mbarrier.try_wait.parity.shared.b64 p, [%1], %2;\n\t"
        "selp.b32 %0, 1, 0, p;\n\t}"
        : "=r"(done) : "r"(a), "r"(parity) : "memory");
    if (!done) {
        asm volatile(
            "{\n\t.reg .pred P1;\n\t"
            "WL_%=:\n\t"
            "mbarrier.try_wait.parity.shared.b64 P1, [%0], %1;\n\t"
            "@P1 bra.uni WD_%=;\n\t"
            "bra.uni WL_%=;\n\t"
            "WD_%=:\n\t}"
            :: "r"(a), "r"(parity) : "memory");
    }
}

// ---------------------------------------------------------------------------
// K1: x'[n,o,p] = sum_c conv_w[o,c] * x[n,c,p] + conv_b[o]
// 64o x 192p per block; thread 4o x 12p (3 quads -> 3 LDS.128 per c);
// 3 blocks/SM. Also zeroes g_colsum.
// ---------------------------------------------------------------------------
#define C1_SW_FLOATS (64 * 65)
#define C1_SX_FLOATS (64 * 192)
#define C1_BYTES ((C1_SW_FLOATS + C1_SX_FLOATS) * 4)   // 65792

__global__ __launch_bounds__(256, 3) void conv_kernel(const float* __restrict__ x,
                                                      const float* __restrict__ w,
                                                      const float* __restrict__ b) {
    extern __shared__ float cs_[];
    float* sW = cs_;                    // [64][65]
    float* sX = cs_ + C1_SW_FLOATS;     // [64][192]
    const int n   = blockIdx.y;
    const int p0  = blockIdx.x * 192;
    const int tid = threadIdx.x;

    // fused colsum zeroing (guarded: grid covers > CS_ELEMS)
    {
        int gidx = (blockIdx.y * gridDim.x + blockIdx.x) * 256 + tid;
        if (gidx < CS_ELEMS) g_colsum[gidx] = 0.0f;
    }

    for (int i = tid; i < 4096; i += 256)
        sW[(i >> 6) * 65 + (i & 63)] = w[i];

    const float* xb = x + n * CIN * PP;
    #pragma unroll
    for (int r = 0; r < 12; r++) {
        int idx = tid + 256 * r;          // float4 index 0..3071
        int c = idx / 48, p4 = idx % 48;
        ((float4*)sX)[c * 48 + p4] = *((const float4*)(xb + c * PP + p0) + p4);
    }
    __syncthreads();

    const int ob = tid >> 4;   // 0..15 -> o = ob + 16*i
    const int px = tid & 15;   // p quads: 4*px + 64*j, j=0..2
    ull acc2[4][6];            // [o][j*2 + half]
    #pragma unroll
    for (int i = 0; i < 4; i++)
        #pragma unroll
        for (int j = 0; j < 6; j++) acc2[i][j] = 0ull;

    #pragma unroll 4
    for (int c = 0; c < 64; c++) {
        ulonglong2 xv[3];
        #pragma unroll
        for (int j = 0; j < 3; j++)
            xv[j] = *(const ulonglong2*)&sX[c * 192 + 4 * px + 64 * j];
        ull wv[4];
        #pragma unroll
        for (int i = 0; i < 4; i++) wv[i] = splat2(sW[(ob + 16 * i) * 65 + c]);
        #pragma unroll
        for (int i = 0; i < 4; i++)
            #pragma unroll
            for (int j = 0; j < 3; j++) {
                acc2[i][2 * j]     = fma2(wv[i], xv[j].x, acc2[i][2 * j]);
                acc2[i][2 * j + 1] = fma2(wv[i], xv[j].y, acc2[i][2 * j + 1]);
            }
    }

    #pragma unroll
    for (int i = 0; i < 4; i++) {
        int o = ob + 16 * i;
        float bo = __ldg(&b[o]);
        float* op = g_xp + (n * CO + o) * PP + p0;
        #pragma unroll
        for (int j = 0; j < 3; j++) {
            float a, bq, cq, d;
            unpack2(acc2[i][2 * j], a, bq);
            unpack2(acc2[i][2 * j + 1], cq, d);
            float4 o4; o4.x = a + bo; o4.y = bq + bo; o4.z = cq + bo; o4.w = d + bo;
            *(float4*)&op[4 * px + 64 * j] = o4;
        }
    }
}

// ---------------------------------------------------------------------------
// K2: MLP 7->16->32->64 (ReLU each stage), mask multiply -> Am + colsum.
// Stage 3 re-paired over (w, w+1): hs = natural LDS.64, Am stores = STG.64.
// ---------------------------------------------------------------------------
#define S2_A    0
#define S2_H2   4096
#define S2_W1T  20480
#define S2_B1   20608
#define S2_W2T  20624
#define S2_B2   21136
#define S2_W3T  21168
#define S2_B3   23216
#define S2_FLOATS 23280
#define S2_BYTES  (S2_FLOATS * 4)

__global__ __launch_bounds__(256, 2) void mlp_kernel(
    const float* __restrict__ A,
    const float* __restrict__ w1, const float* __restrict__ b1,
    const float* __restrict__ w2, const float* __restrict__ b2,
    const float* __restrict__ w3, const float* __restrict__ b3,
    float* __restrict__ Am)
{
    extern __shared__ float s[];
    float* sA   = s + S2_A;
    float* sH2  = s + S2_H2;
    float* sW1t = s + S2_W1T; float* sB1 = s + S2_B1;
    float* sW2t = s + S2_W2T; float* sB2 = s + S2_B2;
    float* sW3t = s + S2_W3T; float* sB3 = s + S2_B3;

    const int tid = threadIdx.x;
    const int w0  = blockIdx.x * 32;
    const int v0  = blockIdx.y * 16;
    const int n   = blockIdx.z;

    if (tid < 112) { int c = tid / 7, k = tid % 7; sW1t[k * 16 + c] = w1[tid]; }
    if (tid < 16)  sB1[tid] = b1[tid];
    for (int i = tid; i < 512; i += 256)  { int c = i >> 4, k = i & 15; sW2t[k * 32 + c] = w2[i]; }
    if (tid < 32)  sB2[tid] = b2[tid];
    for (int i = tid; i < 2048; i += 256) { int c = i >> 5, k = i & 31; sW3t[k * 64 + c] = w3[i]; }
    if (tid < 64)  sB3[tid] = b3[tid];

    {
        const int w   = tid & 31;
        const int sub = tid >> 5;
        const float* Ab = A + n * 8 * VV * VV;
        #pragma unroll
        for (int k = 0; k < 8; k++)
            #pragma unroll
            for (int vi = 0; vi < 2; vi++) {
                int v = sub + vi * 8;
                sA[k * 512 + v * 32 + w] = Ab[(k * VV + v0 + v) * VV + w0 + w];
            }
    }
    __syncthreads();

    #pragma unroll
    for (int jj = 0; jj < 2; jj++) {
        const int p = tid + jj * 256;
        float av[7];
        #pragma unroll
        for (int k = 0; k < 7; k++) av[k] = sA[k * 512 + p];

        ull h1p[8];
        #pragma unroll
        for (int ci = 0; ci < 8; ci++) h1p[ci] = *(const ull*)&sB1[2 * ci];
        #pragma unroll
        for (int k = 0; k < 7; k++) {
            ull sv = splat2(av[k]);
            #pragma unroll
            for (int ci = 0; ci < 8; ci++)
                h1p[ci] = fma2(sv, *(const ull*)&sW1t[k * 16 + 2 * ci], h1p[ci]);
        }
        float h1[16];
        #pragma unroll
        for (int ci = 0; ci < 8; ci++) {
            float lo, hi; unpack2(h1p[ci], lo, hi);
            h1[2 * ci]     = fmaxf(lo, 0.0f);
            h1[2 * ci + 1] = fmaxf(hi, 0.0f);
        }

        ull h2p[16];
        #pragma unroll
        for (int ci = 0; ci < 16; ci++) h2p[ci] = *(const ull*)&sB2[2 * ci];
        #pragma unroll
        for (int k = 0; k < 16; k++) {
            ull sv = splat2(h1[k]);
            #pragma unroll
            for (int ci = 0; ci < 16; ci++)
                h2p[ci] = fma2(sv, *(const ull*)&sW2t[k * 32 + 2 * ci], h2p[ci]);
        }
        #pragma unroll
        for (int ci = 0; ci < 16; ci++) {
            float lo, hi; unpack2(h2p[ci], lo, hi);
            sH2[(2 * ci) * 512 + p]     = fmaxf(lo, 0.0f);
            sH2[(2 * ci + 1) * 512 + p] = fmaxf(hi, 0.0f);
        }
    }
    __syncthreads();

    // ---- stage 3: packed over (w, w+1) pairs ----
    {
        const int wp = tid & 15;          // w pair: 2wp, 2wp+1
        const int cb = tid >> 4;          // 0..15 -> c = cb*4 + ci
        float cs0[4], cs1[4];
        #pragma unroll
        for (int ci = 0; ci < 4; ci++) { cs0[ci] = 0.0f; cs1[ci] = 0.0f; }
        ull bp[4];
        #pragma unroll
        for (int ci = 0; ci < 4; ci++) bp[ci] = splat2(sB3[cb * 4 + ci]);

        #pragma unroll
        for (int half = 0; half < 2; half++) {       // 8 v per pass
            ull acc2[4][8];
            #pragma unroll
            for (int ci = 0; ci < 4; ci++)
                #pragma unroll
                for (int vi = 0; vi < 8; vi++) acc2[ci][vi] = bp[ci];

            #pragma unroll 4
            for (int k = 0; k < 32; k++) {
                ull hs[8];
                #pragma unroll
                for (int vi = 0; vi < 8; vi++)
                    hs[vi] = *(const ull*)&sH2[k * 512 + (half * 8 + vi) * 32 + 2 * wp];
                ull wv[4];
                #pragma unroll
                for (int ci = 0; ci < 4; ci++)
                    wv[ci] = splat2(sW3t[k * 64 + cb * 4 + ci]);
                #pragma unroll
                for (int ci = 0; ci < 4; ci++)
                    #pragma unroll
                    for (int vi = 0; vi < 8; vi++)
                        acc2[ci][vi] = fma2(wv[ci], hs[vi], acc2[ci][vi]);
            }

            #pragma unroll
            for (int vi = 0; vi < 8; vi++) {
                const int v = half * 8 + vi;
                const float2 m2 = *(const float2*)&sA[7 * 512 + v * 32 + 2 * wp];
                #pragma unroll
                for (int ci = 0; ci < 4; ci++) {
                    float lo, hi; unpack2(acc2[ci][vi], lo, hi);
                    float a0 = fmaxf(lo, 0.0f) * m2.x;
                    float a1 = fmaxf(hi, 0.0f) * m2.y;
                    const int c = cb * 4 + ci;
                    float2 st; st.x = a0; st.y = a1;
                    *(float2*)&Am[((n * CO + c) * VV + (v0 + v)) * VV + w0 + 2 * wp] = st;
                    cs0[ci] += a0;
                    cs1[ci] += a1;
                }
            }
        }
        #pragma unroll
        for (int ci = 0; ci < 4; ci++) {
            const int c = cb * 4 + ci;
            atomicAdd(&g_colsum[(n * CO + c) * VV + w0 + 2 * wp], cs0[ci]);
            atomicAdd(&g_colsum[(n * CO + c) * VV + w0 + 2 * wp + 1], cs1[ci]);
        }
    }
}

// ---------------------------------------------------------------------------
// K3: warp-specialized streaming GEMM (EXACT R9 config — best measured; at
// the register-file limit, do not touch).
// 192 threads: warps 0-3 consumers (warp tile 32t x 64w, thread tile 8t x 8w),
//              warps 4-5 producers. 4-stage ring, 2 blocks/SM.
// ---------------------------------------------------------------------------
#define BW      128
#define CHUNK_V 32
#define NSTAGE  4
#define STA_FLOATS (CHUNK_V * BW)          // 4096  (An stage)
#define STX_FLOATS (CHUNK_V * TT)          // 2048  (X^T stage: [32 v][64 t] rotated)
#define S3_XOFF    (NSTAGE * STA_FLOATS)
#define S3_DYN_FLOATS (NSTAGE * (STA_FLOATS + STX_FLOATS))   // 24576
#define S3_DYN_BYTES  (S3_DYN_FLOATS * 4)                     // 98304

__global__ __launch_bounds__(192, 2) void out_kernel(float* __restrict__ out,
                                                     float* __restrict__ An)
{
    extern __shared__ float s[];
    float* sAn = s;                 // [4][32][128]
    float* sXT = s + S3_XOFF;       // [4][32][64] transposed, quad-rotated
    __shared__ float sDl[BW];
    __shared__ __align__(8) ull s_mbar[2 * NSTAGE];

    const int tid = threadIdx.x;
    const int w0  = blockIdx.x * BW;
    const int c   = blockIdx.y;
    const int n   = blockIdx.z;
    const int nc  = n * CO + c;

    const uint32_t mb = smem_u32(s_mbar);
    if (tid == 0) {
        #pragma unroll
        for (int st = 0; st < NSTAGE; st++) {
            mbar_init(mb + st * 8, 64);                // full: 64 producer threads
            mbar_init(mb + (NSTAGE + st) * 8, 4);      // empty: 4 consumer warps
        }
    }
    if (tid < BW) {
        float csv = g_colsum[nc * VV + w0 + tid];
        sDl[tid] = 1.0f / (csv + EPS_);
    }
    __syncthreads();

    float* Anb = An + nc * VV * VV + w0;
    const float* Xb = g_xp + nc * PP;
    const int wid = tid >> 5;

    if (wid >= 4) {
        // ----------------- PRODUCERS (2 warps, 64 threads) -----------------
        const int ptid = tid - 128;   // 0..63
        int stage = 0, ph = 1;
        for (int kc = 0; kc < 12; kc++) {
            float4 curA[16];
            #pragma unroll
            for (int q = 0; q < 16; q++) {
                int idx = ptid + 64 * q;
                int row = idx >> 5, c4 = idx & 31;
                curA[q] = *((const float4*)(Anb + (kc * CHUNK_V + row) * VV) + c4);
            }
            float4 curX[8];
            #pragma unroll
            for (int q = 0; q < 8; q++) {
                int idx = ptid + 64 * q;     // 0..511
                int t = idx >> 3, v4 = idx & 7;
                curX[q] = *((const float4*)(Xb + t * VV + kc * CHUNK_V) + v4);
            }
            mbar_wait(mb + (NSTAGE + stage) * 8, ph);
            float* bufA = sAn + stage * STA_FLOATS;
            float* bufX = sXT + stage * STX_FLOATS;
            #pragma unroll
            for (int q = 0; q < 16; q++) {
                int idx = ptid + 64 * q;
                int row = idx >> 5, c4 = idx & 31;
                ((float4*)bufA)[row * 32 + c4] = curA[q];
                const float4 d4 = ((const float4*)sDl)[c4];
                float4 o4;
                o4.x = curA[q].x * d4.x; o4.y = curA[q].y * d4.y;
                o4.z = curA[q].z * d4.z; o4.w = curA[q].w * d4.w;
                *((float4*)(Anb + (kc * CHUNK_V + row) * VV) + c4) = o4;
            }
            // X^T scatter: X[t][v] -> bufX[v][rotated t], conflict-free
            #pragma unroll
            for (int q = 0; q < 8; q++) {
                int idx = ptid + 64 * q;
                int t = idx >> 3, v4 = idx & 7;
                int base = (((t >> 2) + v4) & 15) * 4 + (t & 3);
                const float* cx = (const float*)&curX[q];
                #pragma unroll
                for (int k = 0; k < 4; k++)
                    bufX[(v4 * 4 + k) * 64 + base] = cx[k];
            }
            mbar_arrive(mb + stage * 8);
            if (++stage == NSTAGE) { stage = 0; ph ^= 1; }
        }
    } else {
        // ----------------- CONSUMERS (4 warps, 128 threads) -----------------
        const int lane = tid & 31;
        const int th = wid >> 1;          // 0..1  t-half
        const int wq = wid & 1;           // 0..1  w-half
        const int tr = lane >> 3;         // 0..3
        const int wc = lane & 7;          // 0..7
        const int wb = wq * 64 + wc * 4;  // owns w: wb..wb+3 and wb+32..wb+35
        const int q0 = th * 8 + tr * 2;   // first t-quad index (t = q0*4..q0*4+7)

        ull acc2[8][4];                   // [t][w-pair]
        #pragma unroll
        for (int i = 0; i < 8; i++)
            #pragma unroll
            for (int j = 0; j < 4; j++) acc2[i][j] = 0ull;

        int stage = 0, ph = 0;
        for (int kc = 0; kc < 12; kc++) {
            mbar_wait(mb + stage * 8, ph);
            const float* bufA = sAn + stage * STA_FLOATS;
            const float* bufX = sXT + stage * STX_FLOATS;
            #pragma unroll
            for (int v4 = 0; v4 < 8; v4++) {
                const int cell0 = (q0 + v4) & 15;
                const int cell1 = (q0 + 1 + v4) & 15;
                #pragma unroll
                for (int vv = 0; vv < 4; vv++) {
                    const int v = v4 * 4 + vv;
                    const float4 x0 = *(const float4*)&bufX[v * 64 + cell0 * 4];
                    const float4 x1 = *(const float4*)&bufX[v * 64 + cell1 * 4];
                    const ulonglong2 a0 = *(const ulonglong2*)&bufA[v * BW + wb];
                    const ulonglong2 a1 = *(const ulonglong2*)&bufA[v * BW + wb + 32];
                    const float* xf0 = (const float*)&x0;
                    const float* xf1 = (const float*)&x1;
                    #pragma unroll
                    for (int tt = 0; tt < 4; tt++) {
                        ull sv = splat2(xf0[tt]);
                        acc2[tt][0] = fma2(sv, a0.x, acc2[tt][0]);
                        acc2[tt][1] = fma2(sv, a0.y, acc2[tt][1]);
                        acc2[tt][2] = fma2(sv, a1.x, acc2[tt][2]);
                        acc2[tt][3] = fma2(sv, a1.y, acc2[tt][3]);
                    }
                    #pragma unroll
                    for (int tt = 0; tt < 4; tt++) {
                        ull sv = splat2(xf1[tt]);
                        acc2[4 + tt][0] = fma2(sv, a0.x, acc2[4 + tt][0]);
                        acc2[4 + tt][1] = fma2(sv, a0.y, acc2[4 + tt][1]);
                        acc2[4 + tt][2] = fma2(sv, a1.x, acc2[4 + tt][2]);
                        acc2[4 + tt][3] = fma2(sv, a1.y, acc2[4 + tt][3]);
                    }
                }
            }
            if (lane == 0) mbar_arrive(mb + (NSTAGE + stage) * 8);
            if (++stage == NSTAGE) { stage = 0; ph ^= 1; }
        }

        // epilogue: scale by Dl, store out (2 float4 per t)
        const float4 d0 = *(const float4*)&sDl[wb];
        const float4 d1 = *(const float4*)&sDl[wb + 32];
        float* ob = out + nc * PP + w0;
        const int t0 = q0 * 4;
        #pragma unroll
        for (int tt = 0; tt < 8; tt++) {
            const int t = t0 + tt;
            float r0, r1, r2, r3, r4, r5, r6, r7;
            unpack2(acc2[tt][0], r0, r1);
            unpack2(acc2[tt][1], r2, r3);
            unpack2(acc2[tt][2], r4, r5);
            unpack2(acc2[tt][3], r6, r7);
            float4 o0; o0.x = r0 * d0.x; o0.y = r1 * d0.y; o0.z = r2 * d0.z; o0.w = r3 * d0.w;
            float4 o1; o1.x = r4 * d1.x; o1.y = r5 * d1.y; o1.z = r6 * d1.z; o1.w = r7 * d1.w;
            *(float4*)&ob[t * VV + wb] = o0;
            *(float4*)&ob[t * VV + wb + 32] = o1;
        }
    }
}

// ---------------------------------------------------------------------------
extern "C" void kernel_launch(void* const* d_in, const int* in_sizes, int n_in,
                              void* d_out, int out_size) {
    const float* x      = (const float*)d_in[0];
    const float* A      = (const float*)d_in[1];
    const float* conv_w = (const float*)d_in[2];
    const float* conv_b = (const float*)d_in[3];
    const float* w1     = (const float*)d_in[4];
    const float* b1     = (const float*)d_in[5];
    const float* w2     = (const float*)d_in[6];
    const float* b2     = (const float*)d_in[7];
    const float* w3     = (const float*)d_in[8];
    const float* b3     = (const float*)d_in[9];

    float* out = (float*)d_out;
    float* An  = out + XP_ELEMS;   // tuple layout: out first, then An

    cudaFuncSetAttribute(conv_kernel, cudaFuncAttributeMaxDynamicSharedMemorySize, C1_BYTES);
    cudaFuncSetAttribute(mlp_kernel, cudaFuncAttributeMaxDynamicSharedMemorySize, S2_BYTES);
    cudaFuncSetAttribute(out_kernel, cudaFuncAttributeMaxDynamicSharedMemorySize, S3_DYN_BYTES);

    conv_kernel<<<dim3(PP / 192, NB), 256, C1_BYTES>>>(x, conv_w, conv_b);
    mlp_kernel<<<dim3(VV / 32, VV / 16, NB), 256, S2_BYTES>>>(A, w1, b1, w2, b2, w3, b3, An);
    out_kernel<<<dim3(VV / BW, CO, NB), 192, S3_DYN_BYTES>>>(out, An);
}

// round 17
// speedup vs baseline: 1.0438x; 1.0438x over previous
#include <cuda_runtime.h>
#include <cstdint>

#define EPS_ 0.001f

// Problem constants
#define NB   16
#define CIN  64
#define CO   64
#define TT   64
#define VV   384
#define PP   (TT*VV)          // 24576 positions per (n, channel)
#define XP_ELEMS  (NB*CO*PP)  // 25165824
#define CS_ELEMS  (NB*CO*VV)  // 393216

typedef unsigned long long ull;

// Scratch (no cudaMalloc allowed)
__device__ float g_xp[XP_ELEMS];
__device__ float g_colsum[CS_ELEMS];

// ---------------------------------------------------------------------------
// packed f32x2 helpers
// ---------------------------------------------------------------------------
__device__ __forceinline__ ull pack2(float lo, float hi) {
    ull r; asm("mov.b64 %0, {%1, %2};" : "=l"(r) : "f"(lo), "f"(hi)); return r;
}
__device__ __forceinline__ ull splat2(float v) {
    ull r; asm("mov.b64 %0, {%1, %1};" : "=l"(r) : "f"(v)); return r;
}
__device__ __forceinline__ void unpack2(ull p, float& lo, float& hi) {
    asm("mov.b64 {%0, %1}, %2;" : "=f"(lo), "=f"(hi) : "l"(p));
}
__device__ __forceinline__ ull fma2(ull a, ull b, ull c) {
    ull d; asm("fma.rn.f32x2 %0, %1, %2, %3;" : "=l"(d) : "l"(a), "l"(b), "l"(c)); return d;
}

// ---------------------------------------------------------------------------
// mbarrier helpers
// ---------------------------------------------------------------------------
__device__ __forceinline__ uint32_t smem_u32(const void* p) {
    uint32_t a;
    asm("{ .reg .u64 t; cvta.to.shared.u64 t, %1; cvt.u32.u64 %0, t; }" : "=r"(a) : "l"(p));
    return a;
}
__device__ __forceinline__ void mbar_init(uint32_t a, uint32_t cnt) {
    asm volatile("mbarrier.init.shared.b64 [%0], %1;" :: "r"(a), "r"(cnt) : "memory");
}
__device__ __forceinline__ void mbar_arrive(uint32_t a) {
    asm volatile("mbarrier.arrive.shared.b64 _, [%0];" :: "r"(a) : "memory");
}
__device__ __forceinline__ void mbar_wait(uint32_t a, uint32_t parity) {
    uint32_t done;
    asm volatile(
        "{\n\t.reg .pred p;\n\t"
        "mbarrier.try_wait.parity.shared.b64 p, [%1], %2;\n\t"
        "selp.b32 %0, 1, 0, p;\n\t}"
        : "=r"(done) : "r"(a), "r"(parity) : "memory");
    if (!done) {
        asm volatile(
            "{\n\t.reg .pred P1;\n\t"
            "WL_%=:\n\t"
            "mbarrier.try_wait.parity.shared.b64 P1, [%0], %1;\n\t"
            "@P1 bra.uni WD_%=;\n\t"
            "bra.uni WL_%=;\n\t"
            "WD_%=:\n\t}"
            :: "r"(a), "r"(parity) : "memory");
    }
}

// ---------------------------------------------------------------------------
// K1: x'[n,o,p] = sum_c conv_w[o,c] * x[n,c,p] + conv_b[o]
// 64o x 192p per block; thread 4o x 12p (24 packed acc); 3 blocks/SM.
// Also zeroes g_colsum.
// ---------------------------------------------------------------------------
#define C1_SW_FLOATS (64 * 65)
#define C1_SX_FLOATS (64 * 192)
#define C1_BYTES ((C1_SW_FLOATS + C1_SX_FLOATS) * 4)   // 65792

__global__ __launch_bounds__(256, 3) void conv_kernel(const float* __restrict__ x,
                                                      const float* __restrict__ w,
                                                      const float* __restrict__ b) {
    extern __shared__ float cs_[];
    float* sW = cs_;                    // [64][65]
    float* sX = cs_ + C1_SW_FLOATS;     // [64][192]
    const int n   = blockIdx.y;
    const int p0  = blockIdx.x * 192;
    const int tid = threadIdx.x;

    // fused colsum zeroing (guarded: grid covers > CS_ELEMS)
    {
        int gidx = (blockIdx.y * gridDim.x + blockIdx.x) * 256 + tid;
        if (gidx < CS_ELEMS) g_colsum[gidx] = 0.0f;
    }

    for (int i = tid; i < 4096; i += 256)
        sW[(i >> 6) * 65 + (i & 63)] = w[i];

    const float* xb = x + n * CIN * PP;
    #pragma unroll
    for (int r = 0; r < 12; r++) {
        int idx = tid + 256 * r;          // float4 index 0..3071
        int c = idx / 48, p4 = idx % 48;
        ((float4*)sX)[c * 48 + p4] = *((const float4*)(xb + c * PP + p0) + p4);
    }
    __syncthreads();

    const int ob = tid >> 4;   // 0..15 -> o = ob + 16*i
    const int px = tid & 15;   // p pairs: 2*px + 32*j, j=0..5
    ull acc2[4][6];
    #pragma unroll
    for (int i = 0; i < 4; i++)
        #pragma unroll
        for (int j = 0; j < 6; j++) acc2[i][j] = 0ull;

    #pragma unroll 4
    for (int c = 0; c < 64; c++) {
        ull xv[6];
        #pragma unroll
        for (int j = 0; j < 6; j++) xv[j] = *(const ull*)&sX[c * 192 + 2 * px + 32 * j];
        ull wv[4];
        #pragma unroll
        for (int i = 0; i < 4; i++) wv[i] = splat2(sW[(ob + 16 * i) * 65 + c]);
        #pragma unroll
        for (int i = 0; i < 4; i++)
            #pragma unroll
            for (int j = 0; j < 6; j++) acc2[i][j] = fma2(wv[i], xv[j], acc2[i][j]);
    }

    #pragma unroll
    for (int i = 0; i < 4; i++) {
        int o = ob + 16 * i;
        float bo = __ldg(&b[o]);
        float* op = g_xp + (n * CO + o) * PP + p0;
        #pragma unroll
        for (int j = 0; j < 6; j++) {
            float lo, hi; unpack2(acc2[i][j], lo, hi);
            float2 o2; o2.x = lo + bo; o2.y = hi + bo;
            *(float2*)&op[2 * px + 32 * j] = o2;
        }
    }
}

// ---------------------------------------------------------------------------
// K2: MLP 7->16->32->64 (ReLU each stage), mask multiply -> Am + colsum.
// (R10 version — best measured)
// ---------------------------------------------------------------------------
#define S2_A    0
#define S2_H2   4096
#define S2_W1T  20480
#define S2_B1   20608
#define S2_W2T  20624
#define S2_B2   21136
#define S2_W3T  21168
#define S2_B3   23216
#define S2_FLOATS 23280
#define S2_BYTES  (S2_FLOATS * 4)

__global__ __launch_bounds__(256, 2) void mlp_kernel(
    const float* __restrict__ A,
    const float* __restrict__ w1, const float* __restrict__ b1,
    const float* __restrict__ w2, const float* __restrict__ b2,
    const float* __restrict__ w3, const float* __restrict__ b3,
    float* __restrict__ Am)
{
    extern __shared__ float s[];
    float* sA   = s + S2_A;
    float* sH2  = s + S2_H2;
    float* sW1t = s + S2_W1T; float* sB1 = s + S2_B1;
    float* sW2t = s + S2_W2T; float* sB2 = s + S2_B2;
    float* sW3t = s + S2_W3T; float* sB3 = s + S2_B3;

    const int tid = threadIdx.x;
    const int w0  = blockIdx.x * 32;
    const int v0  = blockIdx.y * 16;
    const int n   = blockIdx.z;

    if (tid < 112) { int c = tid / 7, k = tid % 7; sW1t[k * 16 + c] = w1[tid]; }
    if (tid < 16)  sB1[tid] = b1[tid];
    for (int i = tid; i < 512; i += 256)  { int c = i >> 4, k = i & 15; sW2t[k * 32 + c] = w2[i]; }
    if (tid < 32)  sB2[tid] = b2[tid];
    for (int i = tid; i < 2048; i += 256) { int c = i >> 5, k = i & 31; sW3t[k * 64 + c] = w3[i]; }
    if (tid < 64)  sB3[tid] = b3[tid];

    {
        const int w   = tid & 31;
        const int sub = tid >> 5;
        const float* Ab = A + n * 8 * VV * VV;
        #pragma unroll
        for (int k = 0; k < 8; k++)
            #pragma unroll
            for (int vi = 0; vi < 2; vi++) {
                int v = sub + vi * 8;
                sA[k * 512 + v * 32 + w] = Ab[(k * VV + v0 + v) * VV + w0 + w];
            }
    }
    __syncthreads();

    #pragma unroll
    for (int jj = 0; jj < 2; jj++) {
        const int p = tid + jj * 256;
        float av[7];
        #pragma unroll
        for (int k = 0; k < 7; k++) av[k] = sA[k * 512 + p];

        ull h1p[8];
        #pragma unroll
        for (int ci = 0; ci < 8; ci++) h1p[ci] = *(const ull*)&sB1[2 * ci];
        #pragma unroll
        for (int k = 0; k < 7; k++) {
            ull sv = splat2(av[k]);
            #pragma unroll
            for (int ci = 0; ci < 8; ci++)
                h1p[ci] = fma2(sv, *(const ull*)&sW1t[k * 16 + 2 * ci], h1p[ci]);
        }
        float h1[16];
        #pragma unroll
        for (int ci = 0; ci < 8; ci++) {
            float lo, hi; unpack2(h1p[ci], lo, hi);
            h1[2 * ci]     = fmaxf(lo, 0.0f);
            h1[2 * ci + 1] = fmaxf(hi, 0.0f);
        }

        ull h2p[16];
        #pragma unroll
        for (int ci = 0; ci < 16; ci++) h2p[ci] = *(const ull*)&sB2[2 * ci];
        #pragma unroll
        for (int k = 0; k < 16; k++) {
            ull sv = splat2(h1[k]);
            #pragma unroll
            for (int ci = 0; ci < 16; ci++)
                h2p[ci] = fma2(sv, *(const ull*)&sW2t[k * 32 + 2 * ci], h2p[ci]);
        }
        #pragma unroll
        for (int ci = 0; ci < 16; ci++) {
            float lo, hi; unpack2(h2p[ci], lo, hi);
            sH2[(2 * ci) * 512 + p]     = fmaxf(lo, 0.0f);
            sH2[(2 * ci + 1) * 512 + p] = fmaxf(hi, 0.0f);
        }
    }
    __syncthreads();

    {
        const int w  = tid & 31;
        const int cb = tid >> 5;
        float cs[8];
        #pragma unroll
        for (int i = 0; i < 8; i++) cs[i] = 0.0f;
        ull bp[4];
        #pragma unroll
        for (int ci = 0; ci < 4; ci++) bp[ci] = *(const ull*)&sB3[cb * 8 + 2 * ci];

        #pragma unroll
        for (int half = 0; half < 2; half++) {       // 8 v per pass
            ull acc2[4][8];
            #pragma unroll
            for (int ci = 0; ci < 4; ci++)
                #pragma unroll
                for (int vi = 0; vi < 8; vi++) acc2[ci][vi] = bp[ci];

            #pragma unroll 4
            for (int k = 0; k < 32; k++) {
                ull hs[8];
                #pragma unroll
                for (int vi = 0; vi < 8; vi++)
                    hs[vi] = splat2(sH2[k * 512 + (half * 8 + vi) * 32 + w]);
                ull wv[4];
                #pragma unroll
                for (int ci = 0; ci < 4; ci++)
                    wv[ci] = *(const ull*)&sW3t[k * 64 + cb * 8 + 2 * ci];
                #pragma unroll
                for (int ci = 0; ci < 4; ci++)
                    #pragma unroll
                    for (int vi = 0; vi < 8; vi++)
                        acc2[ci][vi] = fma2(hs[vi], wv[ci], acc2[ci][vi]);
            }

            #pragma unroll
            for (int vi = 0; vi < 8; vi++) {
                const int v = half * 8 + vi;
                float m = sA[7 * 512 + v * 32 + w];
                #pragma unroll
                for (int ci = 0; ci < 4; ci++) {
                    float lo, hi; unpack2(acc2[ci][vi], lo, hi);
                    float a0 = fmaxf(lo, 0.0f) * m;
                    float a1 = fmaxf(hi, 0.0f) * m;
                    int c0 = cb * 8 + 2 * ci;
                    Am[((n * CO + c0)     * VV + (v0 + v)) * VV + w0 + w] = a0;
                    Am[((n * CO + c0 + 1) * VV + (v0 + v)) * VV + w0 + w] = a1;
                    cs[2 * ci]     += a0;
                    cs[2 * ci + 1] += a1;
                }
            }
        }
        #pragma unroll
        for (int i = 0; i < 8; i++)
            atomicAdd(&g_colsum[(n * CO + cb * 8 + i) * VV + w0 + w], cs[i]);
    }
}

// ---------------------------------------------------------------------------
// K3: warp-specialized streaming GEMM (EXACT R9 config — best measured; at
// the register-file limit, do not touch).
// 192 threads: warps 0-3 consumers (warp tile 32t x 64w, thread tile 8t x 8w),
//              warps 4-5 producers. 4-stage ring, 2 blocks/SM.
// ---------------------------------------------------------------------------
#define BW      128
#define CHUNK_V 32
#define NSTAGE  4
#define STA_FLOATS (CHUNK_V * BW)          // 4096  (An stage)
#define STX_FLOATS (CHUNK_V * TT)          // 2048  (X^T stage: [32 v][64 t] rotated)
#define S3_XOFF    (NSTAGE * STA_FLOATS)
#define S3_DYN_FLOATS (NSTAGE * (STA_FLOATS + STX_FLOATS))   // 24576
#define S3_DYN_BYTES  (S3_DYN_FLOATS * 4)                     // 98304

__global__ __launch_bounds__(192, 2) void out_kernel(float* __restrict__ out,
                                                     float* __restrict__ An)
{
    extern __shared__ float s[];
    float* sAn = s;                 // [4][32][128]
    float* sXT = s + S3_XOFF;       // [4][32][64] transposed, quad-rotated
    __shared__ float sDl[BW];
    __shared__ __align__(8) ull s_mbar[2 * NSTAGE];

    const int tid = threadIdx.x;
    const int w0  = blockIdx.x * BW;
    const int c   = blockIdx.y;
    const int n   = blockIdx.z;
    const int nc  = n * CO + c;

    const uint32_t mb = smem_u32(s_mbar);
    if (tid == 0) {
        #pragma unroll
        for (int st = 0; st < NSTAGE; st++) {
            mbar_init(mb + st * 8, 64);                // full: 64 producer threads
            mbar_init(mb + (NSTAGE + st) * 8, 4);      // empty: 4 consumer warps
        }
    }
    if (tid < BW) {
        float csv = g_colsum[nc * VV + w0 + tid];
        sDl[tid] = 1.0f / (csv + EPS_);
    }
    __syncthreads();

    float* Anb = An + nc * VV * VV + w0;
    const float* Xb = g_xp + nc * PP;
    const int wid = tid >> 5;

    if (wid >= 4) {
        // ----------------- PRODUCERS (2 warps, 64 threads) -----------------
        const int ptid = tid - 128;   // 0..63
        int stage = 0, ph = 1;
        for (int kc = 0; kc < 12; kc++) {
            float4 curA[16];
            #pragma unroll
            for (int q = 0; q < 16; q++) {
                int idx = ptid + 64 * q;
                int row = idx >> 5, c4 = idx & 31;
                curA[q] = *((const float4*)(Anb + (kc * CHUNK_V + row) * VV) + c4);
            }
            float4 curX[8];
            #pragma unroll
            for (int q = 0; q < 8; q++) {
                int idx = ptid + 64 * q;     // 0..511
                int t = idx >> 3, v4 = idx & 7;
                curX[q] = *((const float4*)(Xb + t * VV + kc * CHUNK_V) + v4);
            }
            mbar_wait(mb + (NSTAGE + stage) * 8, ph);
            float* bufA = sAn + stage * STA_FLOATS;
            float* bufX = sXT + stage * STX_FLOATS;
            #pragma unroll
            for (int q = 0; q < 16; q++) {
                int idx = ptid + 64 * q;
                int row = idx >> 5, c4 = idx & 31;
                ((float4*)bufA)[row * 32 + c4] = curA[q];
                const float4 d4 = ((const float4*)sDl)[c4];
                float4 o4;
                o4.x = curA[q].x * d4.x; o4.y = curA[q].y * d4.y;
                o4.z = curA[q].z * d4.z; o4.w = curA[q].w * d4.w;
                *((float4*)(Anb + (kc * CHUNK_V + row) * VV) + c4) = o4;
            }
            // X^T scatter: X[t][v] -> bufX[v][rotated t], conflict-free
            #pragma unroll
            for (int q = 0; q < 8; q++) {
                int idx = ptid + 64 * q;
                int t = idx >> 3, v4 = idx & 7;
                int base = (((t >> 2) + v4) & 15) * 4 + (t & 3);
                const float* cx = (const float*)&curX[q];
                #pragma unroll
                for (int k = 0; k < 4; k++)
                    bufX[(v4 * 4 + k) * 64 + base] = cx[k];
            }
            mbar_arrive(mb + stage * 8);
            if (++stage == NSTAGE) { stage = 0; ph ^= 1; }
        }
    } else {
        // ----------------- CONSUMERS (4 warps, 128 threads) -----------------
        const int lane = tid & 31;
        const int th = wid >> 1;          // 0..1  t-half
        const int wq = wid & 1;           // 0..1  w-half
        const int tr = lane >> 3;         // 0..3
        const int wc = lane & 7;          // 0..7
        const int wb = wq * 64 + wc * 4;  // owns w: wb..wb+3 and wb+32..wb+35
        const int q0 = th * 8 + tr * 2;   // first t-quad index (t = q0*4..q0*4+7)

        ull acc2[8][4];                   // [t][w-pair]
        #pragma unroll
        for (int i = 0; i < 8; i++)
            #pragma unroll
            for (int j = 0; j < 4; j++) acc2[i][j] = 0ull;

        int stage = 0, ph = 0;
        for (int kc = 0; kc < 12; kc++) {
            mbar_wait(mb + stage * 8, ph);
            const float* bufA = sAn + stage * STA_FLOATS;
            const float* bufX = sXT + stage * STX_FLOATS;
            #pragma unroll
            for (int v4 = 0; v4 < 8; v4++) {
                const int cell0 = (q0 + v4) & 15;
                const int cell1 = (q0 + 1 + v4) & 15;
                #pragma unroll
                for (int vv = 0; vv < 4; vv++) {
                    const int v = v4 * 4 + vv;
                    const float4 x0 = *(const float4*)&bufX[v * 64 + cell0 * 4];
                    const float4 x1 = *(const float4*)&bufX[v * 64 + cell1 * 4];
                    const ulonglong2 a0 = *(const ulonglong2*)&bufA[v * BW + wb];
                    const ulonglong2 a1 = *(const ulonglong2*)&bufA[v * BW + wb + 32];
                    const float* xf0 = (const float*)&x0;
                    const float* xf1 = (const float*)&x1;
                    #pragma unroll
                    for (int tt = 0; tt < 4; tt++) {
                        ull sv = splat2(xf0[tt]);
                        acc2[tt][0] = fma2(sv, a0.x, acc2[tt][0]);
                        acc2[tt][1] = fma2(sv, a0.y, acc2[tt][1]);
                        acc2[tt][2] = fma2(sv, a1.x, acc2[tt][2]);
                        acc2[tt][3] = fma2(sv, a1.y, acc2[tt][3]);
                    }
                    #pragma unroll
                    for (int tt = 0; tt < 4; tt++) {
                        ull sv = splat2(xf1[tt]);
                        acc2[4 + tt][0] = fma2(sv, a0.x, acc2[4 + tt][0]);
                        acc2[4 + tt][1] = fma2(sv, a0.y, acc2[4 + tt][1]);
                        acc2[4 + tt][2] = fma2(sv, a1.x, acc2[4 + tt][2]);
                        acc2[4 + tt][3] = fma2(sv, a1.y, acc2[4 + tt][3]);
                    }
                }
            }
            if (lane == 0) mbar_arrive(mb + (NSTAGE + stage) * 8);
            if (++stage == NSTAGE) { stage = 0; ph ^= 1; }
        }

        // epilogue: scale by Dl, store out (2 float4 per t)
        const float4 d0 = *(const float4*)&sDl[wb];
        const float4 d1 = *(const float4*)&sDl[wb + 32];
        float* ob = out + nc * PP + w0;
        const int t0 = q0 * 4;
        #pragma unroll
        for (int tt = 0; tt < 8; tt++) {
            const int t = t0 + tt;
            float r0, r1, r2, r3, r4, r5, r6, r7;
            unpack2(acc2[tt][0], r0, r1);
            unpack2(acc2[tt][1], r2, r3);
            unpack2(acc2[tt][2], r4, r5);
            unpack2(acc2[tt][3], r6, r7);
            float4 o0; o0.x = r0 * d0.x; o0.y = r1 * d0.y; o0.z = r2 * d0.z; o0.w = r3 * d0.w;
            float4 o1; o1.x = r4 * d1.x; o1.y = r5 * d1.y; o1.z = r6 * d1.z; o1.w = r7 * d1.w;
            *(float4*)&ob[t * VV + wb] = o0;
            *(float4*)&ob[t * VV + wb + 32] = o1;
        }
    }
}

// ---------------------------------------------------------------------------
extern "C" void kernel_launch(void* const* d_in, const int* in_sizes, int n_in,
                              void* d_out, int out_size) {
    const float* x      = (const float*)d_in[0];
    const float* A      = (const float*)d_in[1];
    const float* conv_w = (const float*)d_in[2];
    const float* conv_b = (const float*)d_in[3];
    const float* w1     = (const float*)d_in[4];
    const float* b1     = (const float*)d_in[5];
    const float* w2     = (const float*)d_in[6];
    const float* b2     = (const float*)d_in[7];
    const float* w3     = (const float*)d_in[8];
    const float* b3     = (const float*)d_in[9];

    float* out = (float*)d_out;
    float* An  = out + XP_ELEMS;   // tuple layout: out first, then An

    cudaFuncSetAttribute(conv_kernel, cudaFuncAttributeMaxDynamicSharedMemorySize, C1_BYTES);
    cudaFuncSetAttribute(mlp_kernel, cudaFuncAttributeMaxDynamicSharedMemorySize, S2_BYTES);
    cudaFuncSetAttribute(out_kernel, cudaFuncAttributeMaxDynamicSharedMemorySize, S3_DYN_BYTES);

    conv_kernel<<<dim3(PP / 192, NB), 256, C1_BYTES>>>(x, conv_w, conv_b);
    mlp_kernel<<<dim3(VV / 32, VV / 16, NB), 256, S2_BYTES>>>(A, w1, b1, w2, b2, w3, b3, An);
    out_kernel<<<dim3(VV / BW, CO, NB), 192, S3_DYN_BYTES>>>(out, An);
}